// round 14
// baseline (speedup 1.0000x reference)
#include <cuda_runtime.h>
#include <cuda_bf16.h>
#include <mma.h>
#include <cstdint>

using namespace nvcuda;

#define NN 50000
#define NN_PAD 50048   // 391 * 128, for unguarded wmma stores into scratch
#define EE 400000
#define HH 4
#define CC 64
#define HC 256   // HH*CC

// GEMM tiling
#define BM 128
#define BN 64
#define BK 64
#define ASTR 72        // smem row stride (bf16): 144B, 16B-aligned, conflict-free
#define GSMEM ((BM * ASTR * 2 + BN * ASTR * 2) * 2)   // 55296 B

// ---------------- scratch (device globals: no runtime allocation allowed) ----
__device__ float  g_XL[(size_t)NN_PAD * HC];  // source transform  [N,H,C]
__device__ float  g_XR[(size_t)NN_PAD * HC];  // target transform  [N,H,C]
__device__ float  g_H1[(size_t)NN_PAD * CC];  // layer-1 output
__device__ __nv_bfloat16 g_Ahi[(size_t)NN_PAD * 128];
__device__ __nv_bfloat16 g_Alo[(size_t)NN_PAD * 128];
__device__ __nv_bfloat16 g_Whi[2 * 256 * 128];
__device__ __nv_bfloat16 g_Wlo[2 * 256 * 128];
__device__ int    g_deg[NN];                  // per-dst degree
__device__ int    g_off[NN + 1];              // CSR offsets
__device__ int    g_cur[NN];                  // scatter cursors
__device__ float4 g_edge[EE];                 // {src_bits, a0,a1,a2} grouped by dst
__device__ int    g_dhist[64];                // degree-bucket histogram
__device__ int    g_dcur[64];                 // degree-bucket cursors
__device__ int    g_nodeord[NN];              // nodes sorted by descending degree

// ---------------- helpers ---------------------------------------------------
__device__ __forceinline__ float lrelu(float v) { return v > 0.f ? v : 0.2f * v; }

// ---- split fp32 matrix into bf16 hi/lo (Markidis). Pads with zeros. --------
__global__ void split_mat(const float* __restrict__ A,
                          __nv_bfloat16* __restrict__ hi,
                          __nv_bfloat16* __restrict__ lo,
                          int quads_real, int quads_total)
{
    int i = blockIdx.x * blockDim.x + threadIdx.x;
    if (i >= quads_total) return;
    float4 v = (i < quads_real) ? ((const float4*)A)[i]
                                : make_float4(0.f, 0.f, 0.f, 0.f);
    __nv_bfloat162 h0, h1, l0, l1;
    h0.x = __float2bfloat16(v.x);  h0.y = __float2bfloat16(v.y);
    h1.x = __float2bfloat16(v.z);  h1.y = __float2bfloat16(v.w);
    l0.x = __float2bfloat16(v.x - __bfloat162float(h0.x));
    l0.y = __float2bfloat16(v.y - __bfloat162float(h0.y));
    l1.x = __float2bfloat16(v.z - __bfloat162float(h1.x));
    l1.y = __float2bfloat16(v.w - __bfloat162float(h1.y));
    ((__nv_bfloat162*)hi)[2 * i]     = h0;
    ((__nv_bfloat162*)hi)[2 * i + 1] = h1;
    ((__nv_bfloat162*)lo)[2 * i]     = l0;
    ((__nv_bfloat162*)lo)[2 * i + 1] = l1;
}

// ---- GEMM: C{0,1}[M,256] = A[M,K] @ W{0,1}[256,K]^T ------------------------
// Inputs pre-split to bf16 hi/lo. 3-term: Ahi*Whi + Ahi*Wlo + Alo*Whi, fp32
// accumulate. CTA: 128x64 tile, 8 warps (4M x 2N, 32x32 each). grid.x 0-3 ->
// W slab 0, 4-7 -> W slab 1 (offset 256*K); n = (bx&3)*64.
__global__ __launch_bounds__(256) void gemm_wmma(
    const __nv_bfloat16* __restrict__ Ahi, const __nv_bfloat16* __restrict__ Alo,
    const __nv_bfloat16* __restrict__ Whi, const __nv_bfloat16* __restrict__ Wlo,
    float* __restrict__ C0, float* __restrict__ C1, int K)
{
    extern __shared__ __nv_bfloat16 sm[];
    __nv_bfloat16* sAhi = sm;
    __nv_bfloat16* sAlo = sAhi + BM * ASTR;
    __nv_bfloat16* sWhi = sAlo + BM * ASTR;
    __nv_bfloat16* sWlo = sWhi + BN * ASTR;

    const int tid  = threadIdx.x;
    const int warp = tid >> 5;
    const int bx   = blockIdx.x;                  // 0..7
    const size_t woff = (bx < 4) ? 0 : (size_t)256 * K;
    float* C       = (bx < 4) ? C0 : C1;
    const int bn   = (bx & 3) * BN;
    const int bm   = blockIdx.y * BM;
    const int wm   = (warp & 3) * 32;
    const int wn   = (warp >> 2) * 32;

    wmma::fragment<wmma::accumulator, 16, 16, 16, float> acc[2][2];
#pragma unroll
    for (int i = 0; i < 2; i++)
#pragma unroll
        for (int j = 0; j < 2; j++) wmma::fill_fragment(acc[i][j], 0.f);

    const int nch = K / BK;
    for (int ch = 0; ch < nch; ch++) {
        for (int i = tid; i < BM * BK / 8; i += 256) {
            int row = i >> 3;
            int c8  = (i & 7) * 8;
            size_t gsrc = (size_t)(bm + row) * K + ch * BK + c8;
            *(uint4*)&sAhi[row * ASTR + c8] = *(const uint4*)(Ahi + gsrc);
            *(uint4*)&sAlo[row * ASTR + c8] = *(const uint4*)(Alo + gsrc);
        }
        for (int i = tid; i < BN * BK / 8; i += 256) {
            int row = i >> 3;
            int c8  = (i & 7) * 8;
            size_t gsrc = woff + (size_t)(bn + row) * K + ch * BK + c8;
            *(uint4*)&sWhi[row * ASTR + c8] = *(const uint4*)(Whi + gsrc);
            *(uint4*)&sWlo[row * ASTR + c8] = *(const uint4*)(Wlo + gsrc);
        }
        __syncthreads();

#pragma unroll
        for (int ks = 0; ks < BK; ks += 16) {
            wmma::fragment<wmma::matrix_a, 16, 16, 16, __nv_bfloat16, wmma::row_major> ahi[2], alo[2];
            wmma::fragment<wmma::matrix_b, 16, 16, 16, __nv_bfloat16, wmma::col_major> bhi[2], blo[2];
#pragma unroll
            for (int i = 0; i < 2; i++) {
                wmma::load_matrix_sync(ahi[i], &sAhi[(wm + 16 * i) * ASTR + ks], ASTR);
                wmma::load_matrix_sync(alo[i], &sAlo[(wm + 16 * i) * ASTR + ks], ASTR);
                wmma::load_matrix_sync(bhi[i], &sWhi[(wn + 16 * i) * ASTR + ks], ASTR);
                wmma::load_matrix_sync(blo[i], &sWlo[(wn + 16 * i) * ASTR + ks], ASTR);
            }
#pragma unroll
            for (int i = 0; i < 2; i++)
#pragma unroll
                for (int j = 0; j < 2; j++) {
                    wmma::mma_sync(acc[i][j], ahi[i], bhi[j], acc[i][j]);
                    wmma::mma_sync(acc[i][j], ahi[i], blo[j], acc[i][j]);
                    wmma::mma_sync(acc[i][j], alo[i], bhi[j], acc[i][j]);
                }
        }
        __syncthreads();
    }

#pragma unroll
    for (int i = 0; i < 2; i++)
#pragma unroll
        for (int j = 0; j < 2; j++)
            wmma::store_matrix_sync(C + (size_t)(bm + wm + 16 * i) * HC + bn + wn + 16 * j,
                                    acc[i][j], HC, wmma::mem_row_major);
}

// ---------------- CSR build (once per call, reused by both layers) ----------
__global__ void csr_count(const int* __restrict__ dst) {
    int e = blockIdx.x * blockDim.x + threadIdx.x;
    if (e < EE) atomicAdd(&g_deg[dst[e]], 1);
}

__global__ __launch_bounds__(1024) void csr_scan() {
    __shared__ int ssum[1024];
    const int T = 1024;
    const int per = (NN + T - 1) / T;
    int t = threadIdx.x;
    int base = t * per;
    int sum = 0;
    for (int i = 0; i < per; i++) {
        int idx = base + i;
        if (idx < NN) sum += g_deg[idx];
    }
    ssum[t] = sum;
    __syncthreads();
    for (int off = 1; off < T; off <<= 1) {
        int u = (t >= off) ? ssum[t - off] : 0;
        __syncthreads();
        ssum[t] += u;
        __syncthreads();
    }
    int run = ssum[t] - sum;
    for (int i = 0; i < per; i++) {
        int idx = base + i;
        if (idx < NN) {
            g_off[idx] = run;
            g_cur[idx] = run;
            run += g_deg[idx];
        }
    }
    if (t == T - 1) g_off[NN] = run;
}

__global__ void csr_scatter(const int* __restrict__ src,
                            const int* __restrict__ dst,
                            const float* __restrict__ ea) {
    int e = blockIdx.x * blockDim.x + threadIdx.x;
    if (e >= EE) return;
    int d = dst[e];
    int p = atomicAdd(&g_cur[d], 1);
    float4 r;
    r.x = __int_as_float(src[e]);
    r.y = ea[(size_t)e * 3 + 0];
    r.z = ea[(size_t)e * 3 + 1];
    r.w = ea[(size_t)e * 3 + 2];
    g_edge[p] = r;
}

// ---------------- degree-descending node order -------------------------------
__device__ __forceinline__ int deg_bucket(int deg) {
    return (deg > 63) ? 0 : (63 - deg);
}
__global__ void deg_hist() {
    __shared__ int sh[64];
    int t = threadIdx.x;
    if (t < 64) sh[t] = 0;
    __syncthreads();
    int n = blockIdx.x * blockDim.x + t;
    if (n < NN) atomicAdd(&sh[deg_bucket(g_off[n + 1] - g_off[n])], 1);
    __syncthreads();
    if (t < 64 && sh[t]) atomicAdd(&g_dhist[t], sh[t]);
}
__global__ void deg_scan() {
    __shared__ int s[64];
    int t = threadIdx.x;
    int my = g_dhist[t];
    s[t] = my;
    __syncthreads();
    for (int off = 1; off < 64; off <<= 1) {
        int u = (t >= off) ? s[t - off] : 0;
        __syncthreads();
        s[t] += u;
        __syncthreads();
    }
    g_dcur[t] = s[t] - my;
}
__global__ void deg_scatter() {
    int n = blockIdx.x * blockDim.x + threadIdx.x;
    if (n >= NN) return;
    int pos = atomicAdd(&g_dcur[deg_bucket(g_off[n + 1] - g_off[n])], 1);
    g_nodeord[pos] = n;
}

// ---- fused gather pass: one warp per dst node, edge loop unrolled x2 --------
// Lane l owns channels [8l, 8l+8) (head = l>>3). Two edges in flight per
// iteration: both edge records then both xl rows issued before any compute,
// doubling MLP on the er->xl dependent chain; the two butterfly/exp chains
// interleave. Softmax ratio is shift-invariant and logits are O(10), so exp()
// without the segment-max shift is exact enough in fp32.
__global__ __launch_bounds__(256) void node_gather(
    const float* __restrict__ We,       // [256,3]
    const float* __restrict__ att,      // [256] flat h*64+c
    const float* __restrict__ bias,     // [64]
    const float* __restrict__ prelu,    // [64]
    float* __restrict__ out, int mode)
{
    int tid = threadIdx.x;
    int widx = blockIdx.x * 8 + (tid >> 5);
    if (widx >= NN) return;
    int lane = tid & 31;
    int n = g_nodeord[widx];
    int f = lane * 8;

    float wa[8], wb[8], wc[8], av[8];
    {
        const float4* wp = reinterpret_cast<const float4*>(We + f * 3);
        float4 q[6];
#pragma unroll
        for (int i = 0; i < 6; i++) q[i] = __ldg(wp + i);
        const float* qf = (const float*)q;
#pragma unroll
        for (int i = 0; i < 8; i++) {
            wa[i] = qf[3 * i + 0];
            wb[i] = qf[3 * i + 1];
            wc[i] = qf[3 * i + 2];
        }
        float4 A0 = __ldg((const float4*)(att + f));
        float4 A1 = __ldg((const float4*)(att + f + 4));
        av[0] = A0.x; av[1] = A0.y; av[2] = A0.z; av[3] = A0.w;
        av[4] = A1.x; av[5] = A1.y; av[6] = A1.z; av[7] = A1.w;
    }

    const float4* xrp = reinterpret_cast<const float4*>(g_XR) + (size_t)n * (HC / 4);
    float4 R0 = __ldg(xrp + 2 * lane);
    float4 R1 = __ldg(xrp + 2 * lane + 1);
    float xr[8] = { R0.x, R0.y, R0.z, R0.w, R1.x, R1.y, R1.z, R1.w };

    const int o0 = g_off[n];
    const int o1 = g_off[n + 1];
    const float4* XLb = reinterpret_cast<const float4*>(g_XL);

    float acc[8] = { 0.f, 0.f, 0.f, 0.f, 0.f, 0.f, 0.f, 0.f };
    float den = 0.f;

    int j = o0;
    for (; j + 1 < o1; j += 2) {
        // --- issue both edge records, then both xl rows (4 LDG.128 in flight)
        float4 ea = __ldg(&g_edge[j]);
        float4 eb = __ldg(&g_edge[j + 1]);
        const float4* xpa = XLb + (size_t)__float_as_int(ea.x) * (HC / 4);
        const float4* xpb = XLb + (size_t)__float_as_int(eb.x) * (HC / 4);
        float4 A0 = __ldg(xpa + 2 * lane);
        float4 A1 = __ldg(xpa + 2 * lane + 1);
        float4 B0 = __ldg(xpb + 2 * lane);
        float4 B1 = __ldg(xpb + 2 * lane + 1);
        float xla[8] = { A0.x, A0.y, A0.z, A0.w, A1.x, A1.y, A1.z, A1.w };
        float xlb[8] = { B0.x, B0.y, B0.z, B0.w, B1.x, B1.y, B1.z, B1.w };

        float pa = 0.f, pb = 0.f;
#pragma unroll
        for (int i = 0; i < 8; i++) {
            float za = lrelu(xla[i] + xr[i] +
                             fmaf(ea.w, wc[i], fmaf(ea.z, wb[i], ea.y * wa[i])));
            float zb = lrelu(xlb[i] + xr[i] +
                             fmaf(eb.w, wc[i], fmaf(eb.z, wb[i], eb.y * wa[i])));
            pa = fmaf(za, av[i], pa);
            pb = fmaf(zb, av[i], pb);
        }
        // interleaved butterflies (independent chains overlap SHFL latency)
        pa += __shfl_xor_sync(0xffffffffu, pa, 4);
        pb += __shfl_xor_sync(0xffffffffu, pb, 4);
        pa += __shfl_xor_sync(0xffffffffu, pa, 2);
        pb += __shfl_xor_sync(0xffffffffu, pb, 2);
        pa += __shfl_xor_sync(0xffffffffu, pa, 1);
        pb += __shfl_xor_sync(0xffffffffu, pb, 1);
        float wA = __expf(pa);
        float wB = __expf(pb);
        den += wA + wB;
#pragma unroll
        for (int i = 0; i < 8; i++)
            acc[i] = fmaf(wB, xlb[i], fmaf(wA, xla[i], acc[i]));
    }
    if (j < o1) {                       // odd tail
        float4 ea = __ldg(&g_edge[j]);
        const float4* xpa = XLb + (size_t)__float_as_int(ea.x) * (HC / 4);
        float4 A0 = __ldg(xpa + 2 * lane);
        float4 A1 = __ldg(xpa + 2 * lane + 1);
        float xla[8] = { A0.x, A0.y, A0.z, A0.w, A1.x, A1.y, A1.z, A1.w };
        float pa = 0.f;
#pragma unroll
        for (int i = 0; i < 8; i++) {
            float za = lrelu(xla[i] + xr[i] +
                             fmaf(ea.w, wc[i], fmaf(ea.z, wb[i], ea.y * wa[i])));
            pa = fmaf(za, av[i], pa);
        }
        pa += __shfl_xor_sync(0xffffffffu, pa, 4);
        pa += __shfl_xor_sync(0xffffffffu, pa, 2);
        pa += __shfl_xor_sync(0xffffffffu, pa, 1);
        float wA = __expf(pa);
        den += wA;
#pragma unroll
        for (int i = 0; i < 8; i++) acc[i] = fmaf(wA, xla[i], acc[i]);
    }

    float inv = den > 0.f ? __frcp_rn(den) : 0.f;
#pragma unroll
    for (int i = 0; i < 8; i++) acc[i] *= inv;

#pragma unroll
    for (int i = 0; i < 8; i++) {
        acc[i] += __shfl_xor_sync(0xffffffffu, acc[i], 8);
        acc[i] += __shfl_xor_sync(0xffffffffu, acc[i], 16);
    }

    if (lane < 8) {
        int c = lane * 8;
        float4 b0 = __ldg((const float4*)(bias + c));
        float4 b1 = __ldg((const float4*)(bias + c + 4));
        float v[8];
        v[0] = fmaf(0.25f, acc[0], b0.x);
        v[1] = fmaf(0.25f, acc[1], b0.y);
        v[2] = fmaf(0.25f, acc[2], b0.z);
        v[3] = fmaf(0.25f, acc[3], b0.w);
        v[4] = fmaf(0.25f, acc[4], b1.x);
        v[5] = fmaf(0.25f, acc[5], b1.y);
        v[6] = fmaf(0.25f, acc[6], b1.z);
        v[7] = fmaf(0.25f, acc[7], b1.w);
        if (mode == 0) {
            float4* p = (float4*)(g_H1 + (size_t)n * CC + c);
            p[0] = make_float4(v[0], v[1], v[2], v[3]);
            p[1] = make_float4(v[4], v[5], v[6], v[7]);
        } else {
            float4 p0 = __ldg((const float4*)(prelu + c));
            float4 p1 = __ldg((const float4*)(prelu + c + 4));
            float pw[8] = { p0.x, p0.y, p0.z, p0.w, p1.x, p1.y, p1.z, p1.w };
#pragma unroll
            for (int i = 0; i < 8; i++) v[i] = (v[i] >= 0.f) ? v[i] : pw[i] * v[i];
            float4* p = (float4*)(out + (size_t)n * CC + c);
            p[0] = make_float4(v[0], v[1], v[2], v[3]);
            p[1] = make_float4(v[4], v[5], v[6], v[7]);
        }
    }
}

// ---------------- launch -----------------------------------------------------
extern "C" void kernel_launch(void* const* d_in, const int* in_sizes, int n_in,
                              void* d_out, int out_size)
{
    const float* x     = (const float*)d_in[0];
    const int*   ei    = (const int*)  d_in[1];
    const float* eattr = (const float*)d_in[2];
    const float* Wl1   = (const float*)d_in[3];
    const float* Wr1   = (const float*)d_in[4];
    const float* We1   = (const float*)d_in[5];
    const float* att1  = (const float*)d_in[6];
    const float* b1    = (const float*)d_in[7];
    const float* Wl2   = (const float*)d_in[8];
    const float* Wr2   = (const float*)d_in[9];
    const float* We2   = (const float*)d_in[10];
    const float* att2  = (const float*)d_in[11];
    const float* b2    = (const float*)d_in[12];
    const float* prelu = (const float*)d_in[13];
    float* out = (float*)d_out;

    const int* src = ei;
    const int* dst = ei + EE;

    float *XL, *XR, *H1;
    __nv_bfloat16 *Ahi, *Alo, *Whi, *Wlo;
    void *degp, *dhistp;
    cudaGetSymbolAddress((void**)&XL, g_XL);
    cudaGetSymbolAddress((void**)&XR, g_XR);
    cudaGetSymbolAddress((void**)&H1, g_H1);
    cudaGetSymbolAddress((void**)&Ahi, g_Ahi);
    cudaGetSymbolAddress((void**)&Alo, g_Alo);
    cudaGetSymbolAddress((void**)&Whi, g_Whi);
    cudaGetSymbolAddress((void**)&Wlo, g_Wlo);
    cudaGetSymbolAddress(&degp, g_deg);
    cudaGetSymbolAddress(&dhistp, g_dhist);

    cudaFuncSetAttribute(gemm_wmma, cudaFuncAttributeMaxDynamicSharedMemorySize,
                         GSMEM);

    dim3 ggrid(8, NN_PAD / BM);            // 8 x 391
    const int egrid = (EE + 255) / 256;
    const int ngrid = (NN + 7) / 8;
    const int vgrid = (NN + 255) / 256;

    // ---- CSR build + degree-sorted node order (shared by both layers) ----
    cudaMemsetAsync(degp, 0, NN * sizeof(int));
    cudaMemsetAsync(dhistp, 0, 64 * sizeof(int));
    csr_count<<<egrid, 256>>>(dst);
    csr_scan<<<1, 1024>>>();
    csr_scatter<<<egrid, 256>>>(src, dst, eattr);
    deg_hist<<<vgrid, 256>>>();
    deg_scan<<<1, 64>>>();
    deg_scatter<<<vgrid, 256>>>();

    // ---- layer 1 (K=128) ----
    {
        const int K = 128;
        int aq_real = NN * K / 4, aq_tot = NN_PAD * K / 4;
        int wq = 256 * K / 4;
        split_mat<<<(aq_tot + 255) / 256, 256>>>(x, Ahi, Alo, aq_real, aq_tot);
        split_mat<<<(wq + 255) / 256, 256>>>(Wl1, Whi, Wlo, wq, wq);
        split_mat<<<(wq + 255) / 256, 256>>>(Wr1, Whi + (size_t)256 * K,
                                             Wlo + (size_t)256 * K, wq, wq);
        gemm_wmma<<<ggrid, 256, GSMEM>>>(Ahi, Alo, Whi, Wlo, XL, XR, K);
        node_gather<<<ngrid, 256>>>(We1, att1, b1, prelu, out, 0);
    }

    // ---- layer 2 (K=64) ----
    {
        const int K = 64;
        int aq_real = NN * K / 4, aq_tot = NN_PAD * K / 4;
        int wq = 256 * K / 4;
        split_mat<<<(aq_tot + 255) / 256, 256>>>(H1, Ahi, Alo, aq_real, aq_tot);
        split_mat<<<(wq + 255) / 256, 256>>>(Wl2, Whi, Wlo, wq, wq);
        split_mat<<<(wq + 255) / 256, 256>>>(Wr2, Whi + (size_t)256 * K,
                                             Wlo + (size_t)256 * K, wq, wq);
        gemm_wmma<<<ggrid, 256, GSMEM>>>(Ahi, Alo, Whi, Wlo, XL, XR, K);
        node_gather<<<ngrid, 256>>>(We2, att2, b2, prelu, out, 1);
    }
}